// round 9
// baseline (speedup 1.0000x reference)
#include <cuda_runtime.h>
#include <cuda_bf16.h>
#include <math.h>
#include <stdint.h>

#define B_   256
#define IN_  1024
#define D_   512
#define P_   2048
#define SPLITK 4
#define NT_P  (P_ / 64)     // 32 proxy n-tiles per row

// ---------------- scratch (device globals; no allocations allowed) ---------
__device__ float g_feat_part[SPLITK * B_ * D_];   // split-K partials for GEMM1
__device__ float g_featT[B_ * D_];                // tf32-rounded feat
__device__ float g_feat_n2[B_];                   // per-row ||feat||^2 (fp32)
__device__ float g_pmax[B_ * NT_P];               // per (row, n-tile) partial max
__device__ float g_psum[B_ * NT_P];               // per (row, n-tile) partial sumexp
__device__ float g_sy[B_];                        // s[b, y[b]]

// ==================== tf32 mma.sync helpers ================================
__device__ __forceinline__ void mma_tf32(float c[4], const uint32_t a[4], const uint32_t b[2]) {
    asm volatile("mma.sync.aligned.m16n8k8.row.col.f32.tf32.tf32.f32 "
        "{%0,%1,%2,%3}, {%4,%5,%6,%7}, {%8,%9}, {%0,%1,%2,%3};"
        : "+f"(c[0]), "+f"(c[1]), "+f"(c[2]), "+f"(c[3])
        : "r"(a[0]), "r"(a[1]), "r"(a[2]), "r"(a[3]), "r"(b[0]), "r"(b[1]));
}

__device__ __forceinline__ float to_tf32(float x) {
    uint32_t r;
    asm("cvt.rna.tf32.f32 %0, %1;" : "=r"(r) : "f"(x));
    return __uint_as_float(r);
}
__device__ __forceinline__ uint32_t fu(float x) { return __float_as_uint(x); }

// SMEM layout per tile row (Kc=32 floats): float4 at word offset t*8 + jj*4
// holds {X[jj*16+t], X[jj*16+4+t], X[jj*16+8+t], X[jj*16+12+t]} — the two
// k-pairs thread (k-lane t) needs for mma j = 2jj, 2jj+1, in one LDS.128.
// Row stride 44 words (176B): conflict-free fragment LDS.128.
#define RS_W 44

// one Kc=32 chunk of warp mma: warp tile (WM16*16) x (WN8*8)
template<int WM16, int WN8>
__device__ __forceinline__ void chunk_mma(const float* __restrict__ As,
        const float* __restrict__ Bs, int wm, int wn, int g, int t,
        float acc[WM16][WN8][4])
{
#pragma unroll
    for (int jj = 0; jj < 2; jj++) {
        float4 qa[WM16][2];
        float4 qb[WN8];
#pragma unroll
        for (int i = 0; i < WM16; i++) {
            qa[i][0] = *(const float4*)(As + (wm + i * 16 + g) * RS_W + t * 8 + jj * 4);
            qa[i][1] = *(const float4*)(As + (wm + i * 16 + 8 + g) * RS_W + t * 8 + jj * 4);
        }
#pragma unroll
        for (int nn = 0; nn < WN8; nn++)
            qb[nn] = *(const float4*)(Bs + (wn + nn * 8 + g) * RS_W + t * 8 + jj * 4);
#pragma unroll
        for (int i = 0; i < WM16; i++) {
            uint32_t a0[4] = { fu(qa[i][0].x), fu(qa[i][1].x), fu(qa[i][0].y), fu(qa[i][1].y) };
            uint32_t a1[4] = { fu(qa[i][0].z), fu(qa[i][1].z), fu(qa[i][0].w), fu(qa[i][1].w) };
#pragma unroll
            for (int nn = 0; nn < WN8; nn++) {
                uint32_t b0[2] = { fu(qb[nn].x), fu(qb[nn].y) };
                uint32_t b1[2] = { fu(qb[nn].z), fu(qb[nn].w) };
                mma_tf32(acc[i][nn], a0, b0);
                mma_tf32(acc[i][nn], a1, b1);
            }
        }
    }
}

// ---------------- GEMM1: split-K partials of x @ Wb^T (64x64, 512 thr) -----
__global__ __launch_bounds__(512, 1)
void gemm1_mma(const float* __restrict__ x, const float* __restrict__ Wb)
{
    extern __shared__ __align__(16) float smem[];
    constexpr int TW = 64 * RS_W;
    constexpr int STG = 2 * TW;

    const int tid = threadIdx.x, wid = tid >> 5, lane = tid & 31;
    const int g = lane >> 2, t = lane & 3;
    const int n0 = blockIdx.x * 64, m0 = blockIdx.y * 64;
    const int kb = blockIdx.z * (IN_ / SPLITK);
    const int wm = (wid & 3) * 16, wn = (wid >> 2) * 16;

    const bool isA = tid < 128, act = tid < 256;
    const int task = isA ? tid : tid - 128;
    const int r = task >> 1, jj = task & 1;
    const float* src = isA ? (x + (size_t)(m0 + r) * IN_) : (Wb + (size_t)(n0 + r) * IN_);
    const int seg = isA ? 0 : TW;

    float acc[1][2][4] = {};
    float4 v[2][4];                 // two in-flight register stages

    auto ld = [&](int c, float4* vv) {
        if (act) {
            const float4* p = (const float4*)(src + kb + c * 32 + jj * 16);
            vv[0] = p[0]; vv[1] = p[1]; vv[2] = p[2]; vv[3] = p[3];
        }
    };
    auto st = [&](int c, const float4* vv) {
        if (act) {
            float a0[4] = {vv[0].x, vv[0].y, vv[0].z, vv[0].w};
            float a1[4] = {vv[1].x, vv[1].y, vv[1].z, vv[1].w};
            float a2[4] = {vv[2].x, vv[2].y, vv[2].z, vv[2].w};
            float a3[4] = {vv[3].x, vv[3].y, vv[3].z, vv[3].w};
            float* dst = smem + (c & 1) * STG + seg + r * RS_W + jj * 4;
#pragma unroll
            for (int tt = 0; tt < 4; tt++)
                *(float4*)(dst + tt * 8) = make_float4(to_tf32(a0[tt]), to_tf32(a1[tt]),
                                                       to_tf32(a2[tt]), to_tf32(a3[tt]));
        }
    };

    constexpr int NCH = (IN_ / SPLITK) / 32;    // 8
    ld(0, v[0]); st(0, v[0]); ld(1, v[1]); __syncthreads();
    for (int c = 0; c < NCH; c++) {
        if (c + 2 < NCH) ld(c + 2, v[c & 1]);   // 2-ahead: full LDG latency hidden
        const float* stg = smem + (c & 1) * STG;
        chunk_mma<1, 2>(stg, stg + TW, wm, wn, g, t, acc);
        if (c + 1 < NCH) { st(c + 1, v[(c + 1) & 1]); __syncthreads(); }
    }

    float* dst = g_feat_part + (size_t)blockIdx.z * B_ * D_;
    const int m = m0 + wm + g;
#pragma unroll
    for (int nn = 0; nn < 2; nn++) {
        int n = n0 + wn + nn * 8 + 2 * t;
        *(float2*)(dst + (size_t)m * D_ + n)       = make_float2(acc[0][nn][0], acc[0][nn][1]);
        *(float2*)(dst + (size_t)(m + 8) * D_ + n) = make_float2(acc[0][nn][2], acc[0][nn][3]);
    }
}

// ---------------- combine: split-K reduce + bias + round + row norm --------
__global__ void combine_feat_kernel(const float* __restrict__ bb)
{
    const int row  = blockIdx.x * 8 + (threadIdx.x >> 5);
    const int lane = threadIdx.x & 31;
    const float4* bias4 = (const float4*)bb;
    float4* dst4 = (float4*)(g_featT + (size_t)row * D_);
    float sq = 0.f;
#pragma unroll
    for (int i = 0; i < 4; i++) {
        int c4 = lane + 32 * i;
        float4 s = bias4[c4];
#pragma unroll
        for (int z = 0; z < SPLITK; z++) {
            float4 p = *(const float4*)(g_feat_part + (size_t)z * B_ * D_
                                        + (size_t)row * D_ + c4 * 4);
            s.x += p.x; s.y += p.y; s.z += p.z; s.w += p.w;
        }
        sq += s.x * s.x + s.y * s.y + s.z * s.z + s.w * s.w;
        s.x = to_tf32(s.x); s.y = to_tf32(s.y); s.z = to_tf32(s.z); s.w = to_tf32(s.w);
        dst4[c4] = s;
    }
#pragma unroll
    for (int o = 16; o; o >>= 1) sq += __shfl_xor_sync(0xffffffffu, sq, o);
    if (lane == 0) g_feat_n2[row] = sq;
}

// ---------------- fused GEMM2 (out) + GEMM3 (softmax partials), 512 thr ----
__global__ __launch_bounds__(512, 1)
void gemm23_mma(const float* __restrict__ Wm, const float* __restrict__ bm,
                const float* __restrict__ proxies, const int* __restrict__ y,
                float* __restrict__ out)
{
    extern __shared__ __align__(16) float smem[];
    constexpr int TAW = 128 * RS_W;
    constexpr int TBW = 64 * RS_W;
    constexpr int STG = TAW + TBW;
    float* pn2s = smem + 2 * STG;               // [64]
    float* pmx  = pn2s + 64;                    // [128][4]
    float* psm  = pmx + 512;                    // [128][4]

    const int tid = threadIdx.x, wid = tid >> 5, lane = tid & 31;
    const int g = lane >> 2, t = lane & 3;
    const int nt = blockIdx.x;                  // 0..63
    const bool isp = (nt >= 32);
    const int n0 = (nt & 31) * 64;
    const int m0 = blockIdx.y * 128;
    const float* Bmat = isp ? proxies : Wm;
    const int wm = (wid & 3) * 32, wn = (wid >> 2) * 16, wc = wid >> 2;

    const bool isA = tid < 256, act = tid < 384;
    const int task = isA ? tid : tid - 256;
    const int r = task >> 1, jj = task & 1;
    const float* src = isA ? (g_featT + (size_t)(m0 + r) * D_)
                           : (Bmat + (size_t)(n0 + r) * D_);
    const int seg = isA ? 0 : TAW;

    float acc[2][2][4] = {};
    float4 v[2][4];
    float sq = 0.f;

    auto ld = [&](int c, float4* vv) {
        if (act) {
            const float4* p = (const float4*)(src + c * 32 + jj * 16);
            vv[0] = p[0]; vv[1] = p[1]; vv[2] = p[2]; vv[3] = p[3];
        }
    };
    auto st = [&](int c, const float4* vv) {
        if (act) {
            float a0[4] = {vv[0].x, vv[0].y, vv[0].z, vv[0].w};
            float a1[4] = {vv[1].x, vv[1].y, vv[1].z, vv[1].w};
            float a2[4] = {vv[2].x, vv[2].y, vv[2].z, vv[2].w};
            float a3[4] = {vv[3].x, vv[3].y, vv[3].z, vv[3].w};
            float* dst = smem + (c & 1) * STG + seg + r * RS_W + jj * 4;
            if (isA) {      // feat already tf32-rounded
#pragma unroll
                for (int tt = 0; tt < 4; tt++)
                    *(float4*)(dst + tt * 8) = make_float4(a0[tt], a1[tt], a2[tt], a3[tt]);
            } else {        // B side: fp32 sumsq + round
#pragma unroll
                for (int u = 0; u < 4; u++)
                    sq += a0[u] * a0[u] + a1[u] * a1[u] + a2[u] * a2[u] + a3[u] * a3[u];
#pragma unroll
                for (int tt = 0; tt < 4; tt++)
                    *(float4*)(dst + tt * 8) = make_float4(to_tf32(a0[tt]), to_tf32(a1[tt]),
                                                           to_tf32(a2[tt]), to_tf32(a3[tt]));
            }
        }
    };

    constexpr int NCH = D_ / 32;                // 16
    ld(0, v[0]); st(0, v[0]); ld(1, v[1]); __syncthreads();
    for (int c = 0; c < NCH; c++) {
        if (c + 2 < NCH) ld(c + 2, v[c & 1]);   // 2-ahead: full LDG latency hidden
        const float* stg = smem + (c & 1) * STG;
        chunk_mma<2, 2>(stg, stg + TAW, wm, wn, g, t, acc);
        if (c + 1 < NCH) { st(c + 1, v[(c + 1) & 1]); __syncthreads(); }
    }

    // B-row sumsq: tasks (r,0),(r,1) sit on adjacent lanes -> pair shuffle
    {
        float sb = sq + __shfl_xor_sync(0xffffffffu, sq, 1);
        if (act && !isA && (lane & 1) == 0) pn2s[(tid - 256) >> 1] = sb;
    }
    __syncthreads();

    if (!isp) {
#pragma unroll
        for (int i = 0; i < 2; i++) {
            int m = m0 + wm + i * 16 + g;
#pragma unroll
            for (int nn = 0; nn < 2; nn++) {
                int n = n0 + wn + nn * 8 + 2 * t;
                float bn0 = bm[n], bn1 = bm[n + 1];
                *(float2*)(out + (size_t)m * P_ + n) =
                    make_float2(acc[i][nn][0] + bn0, acc[i][nn][1] + bn1);
                *(float2*)(out + (size_t)(m + 8) * P_ + n) =
                    make_float2(acc[i][nn][2] + bn0, acc[i][nn][3] + bn1);
            }
        }
    } else {
        // proxy: s = 2*dot - fn2 - pn2 in regs -> per-(row, warp) (max, sumexp)
#pragma unroll
        for (int i = 0; i < 2; i++) {
            const int rA = wm + i * 16 + g;
            const int rB = rA + 8;
            const float fa = g_feat_n2[m0 + rA], fb = g_feat_n2[m0 + rB];
            const int ya = y[m0 + rA], yb = y[m0 + rB];
            float sA[4], sB[4];
#pragma unroll
            for (int nn = 0; nn < 2; nn++) {
                int nl = wn + nn * 8 + 2 * t;
                float p0 = pn2s[nl], p1 = pn2s[nl + 1];
                sA[nn * 2 + 0] = 2.f * acc[i][nn][0] - fa - p0;
                sA[nn * 2 + 1] = 2.f * acc[i][nn][1] - fa - p1;
                sB[nn * 2 + 0] = 2.f * acc[i][nn][2] - fb - p0;
                sB[nn * 2 + 1] = 2.f * acc[i][nn][3] - fb - p1;
                int n = n0 + nl;
                if (n     == ya) g_sy[m0 + rA] = sA[nn * 2 + 0];
                if (n + 1 == ya) g_sy[m0 + rA] = sA[nn * 2 + 1];
                if (n     == yb) g_sy[m0 + rB] = sB[nn * 2 + 0];
                if (n + 1 == yb) g_sy[m0 + rB] = sB[nn * 2 + 1];
            }
            float mA = fmaxf(fmaxf(sA[0], sA[1]), fmaxf(sA[2], sA[3]));
            float mB = fmaxf(fmaxf(sB[0], sB[1]), fmaxf(sB[2], sB[3]));
            float eA = expf(sA[0] - mA) + expf(sA[1] - mA)
                     + expf(sA[2] - mA) + expf(sA[3] - mA);
            float eB = expf(sB[0] - mB) + expf(sB[1] - mB)
                     + expf(sB[2] - mB) + expf(sB[3] - mB);
#pragma unroll
            for (int o = 1; o <= 2; o <<= 1) {
                float mA2 = __shfl_xor_sync(0xffffffffu, mA, o);
                float eA2 = __shfl_xor_sync(0xffffffffu, eA, o);
                float mB2 = __shfl_xor_sync(0xffffffffu, mB, o);
                float eB2 = __shfl_xor_sync(0xffffffffu, eB, o);
                float M = fmaxf(mA, mA2);
                eA = eA * expf(mA - M) + eA2 * expf(mA2 - M); mA = M;
                M = fmaxf(mB, mB2);
                eB = eB * expf(mB - M) + eB2 * expf(mB2 - M); mB = M;
            }
            if (t == 0) {
                pmx[rA * 4 + wc] = mA; psm[rA * 4 + wc] = eA;
                pmx[rB * 4 + wc] = mB; psm[rB * 4 + wc] = eB;
            }
        }
        __syncthreads();
        if (tid < 128) {
            float4 m4 = *(const float4*)(pmx + tid * 4);
            float4 s4 = *(const float4*)(psm + tid * 4);
            float M = fmaxf(fmaxf(m4.x, m4.y), fmaxf(m4.z, m4.w));
            float S = s4.x * expf(m4.x - M) + s4.y * expf(m4.y - M)
                    + s4.z * expf(m4.z - M) + s4.w * expf(m4.w - M);
            int idx = (m0 + tid) * NT_P + (nt - 32);
            g_pmax[idx] = M;
            g_psum[idx] = S;
        }
    }
}

// ---------------- finalize: logsumexp combine + both scalars (1 block) -----
__global__ __launch_bounds__(1024, 1)
void finalize_kernel(float* __restrict__ out)
{
    __shared__ float r1[256], r2[256];
    const int tid = threadIdx.x;
    const int b = tid >> 2, t = tid & 2;            // t in {0,2}: 2 half-rows... no:
    // 4 threads per row, thread q = tid & 3 handles pairs [q*8, q*8+8)
    const int q = tid & 3;
    const float4* pm = (const float4*)(g_pmax + b * NT_P + q * 8);
    const float4* ps = (const float4*)(g_psum + b * NT_P + q * 8);
    float4 m0 = pm[0], m1 = pm[1], s0 = ps[0], s1 = ps[1];
    float M = fmaxf(fmaxf(fmaxf(m0.x, m0.y), fmaxf(m0.z, m0.w)),
                    fmaxf(fmaxf(m1.x, m1.y), fmaxf(m1.z, m1.w)));
    float S = s0.x * expf(m0.x - M) + s0.y * expf(m0.y - M)
            + s0.z * expf(m0.z - M) + s0.w * expf(m0.w - M)
            + s1.x * expf(m1.x - M) + s1.y * expf(m1.y - M)
            + s1.z * expf(m1.z - M) + s1.w * expf(m1.w - M);
#pragma unroll
    for (int o = 1; o <= 2; o <<= 1) {
        float M2 = __shfl_xor_sync(0xffffffffu, M, o);
        float S2 = __shfl_xor_sync(0xffffffffu, S, o);
        float Mn = fmaxf(M, M2);
        S = S * expf(M - Mn) + S2 * expf(M2 - Mn);
        M = Mn;
    }
    if (q == 0) {
        r1[b] = g_sy[b] - M - logf(S);              // logp[b, y[b]]
        r2[b] = sqrtf(g_feat_n2[b]);
    }
    __syncthreads();
    for (int st = 128; st > 0; st >>= 1) {
        if (tid < st) { r1[tid] += r1[tid + st]; r2[tid] += r2[tid + st]; }
        __syncthreads();
    }
    if (tid == 0) {
        out[(size_t)B_ * P_]     = -r1[0] / (float)B_;  // loss
        out[(size_t)B_ * P_ + 1] =  r2[0] / (float)B_;  // reg_e
    }
    (void)t;
}

// ---------------- launch ----------------------------------------------------
extern "C" void kernel_launch(void* const* d_in, const int* in_sizes, int n_in,
                              void* d_out, int out_size)
{
    const float* x       = (const float*)d_in[0];
    const int*   y       = (const int*)  d_in[1];
    const float* Wb      = (const float*)d_in[2];
    const float* bb      = (const float*)d_in[3];
    const float* Wm      = (const float*)d_in[4];
    const float* bm      = (const float*)d_in[5];
    const float* proxies = (const float*)d_in[6];
    float* out = (float*)d_out;

    const int SMEM1 = 4 * 64 * RS_W * 4;                        // 45056 B
    const int SMEM2 = (2 * (128 + 64) * RS_W + 64 + 1024) * 4;  // 71936 B
    cudaFuncSetAttribute(gemm1_mma,  cudaFuncAttributeMaxDynamicSharedMemorySize, SMEM1);
    cudaFuncSetAttribute(gemm23_mma, cudaFuncAttributeMaxDynamicSharedMemorySize, SMEM2);

    // 1) feat partials: (8, 4, 4) = 128 CTAs, 512 thr
    gemm1_mma<<<dim3(D_ / 64, B_ / 64, SPLITK), 512, SMEM1>>>(x, Wb);
    // 2) combine + bias + round + row norms
    combine_feat_kernel<<<B_ / 8, 256>>>(bb);
    // 3) fused out-head + proxy softmax partials: (64, 2) = 128 CTAs, 512 thr
    gemm23_mma<<<dim3(64, B_ / 128), 512, SMEM2>>>(Wm, bm, proxies, y, out);
    // 4) logsumexp combine + scalars (single block, 1024 thr)
    finalize_kernel<<<1, 1024>>>(out);
}

// round 10
// speedup vs baseline: 1.1499x; 1.1499x over previous
#include <cuda_runtime.h>
#include <cuda_bf16.h>
#include <math.h>
#include <stdint.h>

#define B_   256
#define IN_  1024
#define D_   512
#define P_   2048
#define SPLITK 4
#define NT_P  (P_ / 64)     // 32 proxy n-tiles per row

// ---------------- scratch (device globals; no allocations allowed) ---------
__device__ float g_feat_part[SPLITK * B_ * D_];   // split-K partials for GEMM1
__device__ float g_featT[B_ * D_];                // tf32-rounded feat
__device__ float g_feat_n2[B_];                   // per-row ||feat||^2 (fp32)
__device__ float g_pmax[B_ * NT_P];               // per (row, n-tile) partial max
__device__ float g_psum[B_ * NT_P];               // per (row, n-tile) partial sumexp
__device__ float g_sy[B_];                        // s[b, y[b]]
__device__ int   g_done;                          // proxy-CTA completion counter

// ==================== tf32 mma.sync helpers ================================
__device__ __forceinline__ void mma_tf32(float c[4], const uint32_t a[4], const uint32_t b[2]) {
    asm volatile("mma.sync.aligned.m16n8k8.row.col.f32.tf32.tf32.f32 "
        "{%0,%1,%2,%3}, {%4,%5,%6,%7}, {%8,%9}, {%0,%1,%2,%3};"
        : "+f"(c[0]), "+f"(c[1]), "+f"(c[2]), "+f"(c[3])
        : "r"(a[0]), "r"(a[1]), "r"(a[2]), "r"(a[3]), "r"(b[0]), "r"(b[1]));
}

__device__ __forceinline__ float to_tf32(float x) {
    uint32_t r;
    asm("cvt.rna.tf32.f32 %0, %1;" : "=r"(r) : "f"(x));
    return __uint_as_float(r);
}
__device__ __forceinline__ uint32_t fu(float x) { return __float_as_uint(x); }

// SMEM layout per tile row (Kc=32 floats): float4 at word offset t*8 + jj*4
// holds the two k-pairs thread (k-lane t) needs for mma j = 2jj, 2jj+1 in one
// LDS.128. Row stride 44 words (176B): conflict-free fragment LDS.128.
#define RS_W 44

template<int WM16, int WN8>
__device__ __forceinline__ void chunk_mma(const float* __restrict__ As,
        const float* __restrict__ Bs, int wm, int wn, int g, int t,
        float acc[WM16][WN8][4])
{
#pragma unroll
    for (int jj = 0; jj < 2; jj++) {
        float4 qa[WM16][2];
        float4 qb[WN8];
#pragma unroll
        for (int i = 0; i < WM16; i++) {
            qa[i][0] = *(const float4*)(As + (wm + i * 16 + g) * RS_W + t * 8 + jj * 4);
            qa[i][1] = *(const float4*)(As + (wm + i * 16 + 8 + g) * RS_W + t * 8 + jj * 4);
        }
#pragma unroll
        for (int nn = 0; nn < WN8; nn++)
            qb[nn] = *(const float4*)(Bs + (wn + nn * 8 + g) * RS_W + t * 8 + jj * 4);
#pragma unroll
        for (int i = 0; i < WM16; i++) {
            uint32_t a0[4] = { fu(qa[i][0].x), fu(qa[i][1].x), fu(qa[i][0].y), fu(qa[i][1].y) };
            uint32_t a1[4] = { fu(qa[i][0].z), fu(qa[i][1].z), fu(qa[i][0].w), fu(qa[i][1].w) };
#pragma unroll
            for (int nn = 0; nn < WN8; nn++) {
                uint32_t b0[2] = { fu(qb[nn].x), fu(qb[nn].y) };
                uint32_t b1[2] = { fu(qb[nn].z), fu(qb[nn].w) };
                mma_tf32(acc[i][nn], a0, b0);
                mma_tf32(acc[i][nn], a1, b1);
            }
        }
    }
}

// ---------------- GEMM1: split-K partials of x @ Wb^T (64x64, 512 thr) -----
__global__ __launch_bounds__(512, 1)
void gemm1_mma(const float* __restrict__ x, const float* __restrict__ Wb)
{
    extern __shared__ __align__(16) float smem[];
    constexpr int TW = 64 * RS_W;
    constexpr int STG = 2 * TW;

    const int tid = threadIdx.x, wid = tid >> 5, lane = tid & 31;
    const int g = lane >> 2, t = lane & 3;
    const int n0 = blockIdx.x * 64, m0 = blockIdx.y * 64;
    const int kb = blockIdx.z * (IN_ / SPLITK);
    const int wm = (wid & 3) * 16, wn = (wid >> 2) * 16;

    const bool isA = tid < 128, act = tid < 256;
    const int task = isA ? tid : tid - 128;
    const int r = task >> 1, jj = task & 1;
    const float* src = isA ? (x + (size_t)(m0 + r) * IN_) : (Wb + (size_t)(n0 + r) * IN_);
    const int seg = isA ? 0 : TW;

    float acc[1][2][4] = {};
    float4 v[4];

    auto ld = [&](int c) {
        if (act) {
            const float4* p = (const float4*)(src + kb + c * 32 + jj * 16);
            v[0] = p[0]; v[1] = p[1]; v[2] = p[2]; v[3] = p[3];
        }
    };
    auto st = [&](int c) {
        if (act) {
            float a0[4] = {v[0].x, v[0].y, v[0].z, v[0].w};
            float a1[4] = {v[1].x, v[1].y, v[1].z, v[1].w};
            float a2[4] = {v[2].x, v[2].y, v[2].z, v[2].w};
            float a3[4] = {v[3].x, v[3].y, v[3].z, v[3].w};
            float* dst = smem + (c & 1) * STG + seg + r * RS_W + jj * 4;
#pragma unroll
            for (int tt = 0; tt < 4; tt++)
                *(float4*)(dst + tt * 8) = make_float4(to_tf32(a0[tt]), to_tf32(a1[tt]),
                                                       to_tf32(a2[tt]), to_tf32(a3[tt]));
        }
    };

    ld(0); st(0); __syncthreads();
    constexpr int NCH = (IN_ / SPLITK) / 32;    // 8
    for (int c = 0; c < NCH; c++) {
        if (c + 1 < NCH) ld(c + 1);
        const float* stg = smem + (c & 1) * STG;
        chunk_mma<1, 2>(stg, stg + TW, wm, wn, g, t, acc);
        if (c + 1 < NCH) { st(c + 1); __syncthreads(); }
    }

    float* dst = g_feat_part + (size_t)blockIdx.z * B_ * D_;
    const int m = m0 + wm + g;
#pragma unroll
    for (int nn = 0; nn < 2; nn++) {
        int n = n0 + wn + nn * 8 + 2 * t;
        *(float2*)(dst + (size_t)m * D_ + n)       = make_float2(acc[0][nn][0], acc[0][nn][1]);
        *(float2*)(dst + (size_t)(m + 8) * D_ + n) = make_float2(acc[0][nn][2], acc[0][nn][3]);
    }
}

// ---------------- combine: split-K reduce + bias + round + row norm --------
__global__ void combine_feat_kernel(const float* __restrict__ bb)
{
    const int row  = blockIdx.x * 8 + (threadIdx.x >> 5);
    const int lane = threadIdx.x & 31;
    const float4* bias4 = (const float4*)bb;
    float4* dst4 = (float4*)(g_featT + (size_t)row * D_);
    float sq = 0.f;
#pragma unroll
    for (int i = 0; i < 4; i++) {
        int c4 = lane + 32 * i;
        float4 s = bias4[c4];
#pragma unroll
        for (int z = 0; z < SPLITK; z++) {
            float4 p = *(const float4*)(g_feat_part + (size_t)z * B_ * D_
                                        + (size_t)row * D_ + c4 * 4);
            s.x += p.x; s.y += p.y; s.z += p.z; s.w += p.w;
        }
        sq += s.x * s.x + s.y * s.y + s.z * s.z + s.w * s.w;
        s.x = to_tf32(s.x); s.y = to_tf32(s.y); s.z = to_tf32(s.z); s.w = to_tf32(s.w);
        dst4[c4] = s;
    }
#pragma unroll
    for (int o = 16; o; o >>= 1) sq += __shfl_xor_sync(0xffffffffu, sq, o);
    if (lane == 0) g_feat_n2[row] = sq;
}

// ---------------- fused GEMM2 (out) + GEMM3 + last-CTA finalize ------------
// Tile 128(m) x 64(n), K=512. grid (64, 2) = 128 CTAs, 512 thr.
__global__ __launch_bounds__(512, 1)
void gemm23_mma(const float* __restrict__ Wm, const float* __restrict__ bm,
                const float* __restrict__ proxies, const int* __restrict__ y,
                float* __restrict__ out)
{
    extern __shared__ __align__(16) float smem[];
    constexpr int TAW = 128 * RS_W;
    constexpr int TBW = 64 * RS_W;
    constexpr int STG = TAW + TBW;
    float* pn2s = smem + 2 * STG;               // [64]
    float* pmx  = pn2s + 64;                    // [128][4]  (reused by finalize)
    float* psm  = pmx + 512;                    // [128][4]
    int*   flag = (int*)(psm + 512);

    const int tid = threadIdx.x, wid = tid >> 5, lane = tid & 31;
    const int g = lane >> 2, t = lane & 3;
    const int nt = blockIdx.x;                  // 0..63
    const bool isp = (nt >= 32);
    const int n0 = (nt & 31) * 64;
    const int m0 = blockIdx.y * 128;
    const float* Bmat = isp ? proxies : Wm;
    const int wm = (wid & 3) * 32, wn = (wid >> 2) * 16, wc = wid >> 2;

    const bool isA = tid < 256, act = tid < 384;
    const int task = isA ? tid : tid - 256;
    const int r = task >> 1, jj = task & 1;
    const float* src = isA ? (g_featT + (size_t)(m0 + r) * D_)
                           : (Bmat + (size_t)(n0 + r) * D_);
    const int seg = isA ? 0 : TAW;

    float acc[2][2][4] = {};
    float4 v[4];
    float sq = 0.f;

    auto ld = [&](int c) {
        if (act) {
            const float4* p = (const float4*)(src + c * 32 + jj * 16);
            v[0] = p[0]; v[1] = p[1]; v[2] = p[2]; v[3] = p[3];
        }
    };
    auto st = [&](int c) {
        if (act) {
            float a0[4] = {v[0].x, v[0].y, v[0].z, v[0].w};
            float a1[4] = {v[1].x, v[1].y, v[1].z, v[1].w};
            float a2[4] = {v[2].x, v[2].y, v[2].z, v[2].w};
            float a3[4] = {v[3].x, v[3].y, v[3].z, v[3].w};
            float* dst = smem + (c & 1) * STG + seg + r * RS_W + jj * 4;
            if (isA) {      // feat already tf32-rounded
#pragma unroll
                for (int tt = 0; tt < 4; tt++)
                    *(float4*)(dst + tt * 8) = make_float4(a0[tt], a1[tt], a2[tt], a3[tt]);
            } else {        // B side: fp32 sumsq + round
#pragma unroll
                for (int u = 0; u < 4; u++)
                    sq += a0[u] * a0[u] + a1[u] * a1[u] + a2[u] * a2[u] + a3[u] * a3[u];
#pragma unroll
                for (int tt = 0; tt < 4; tt++)
                    *(float4*)(dst + tt * 8) = make_float4(to_tf32(a0[tt]), to_tf32(a1[tt]),
                                                           to_tf32(a2[tt]), to_tf32(a3[tt]));
            }
        }
    };

    ld(0); st(0); __syncthreads();
    constexpr int NCH = D_ / 32;                // 16
    for (int c = 0; c < NCH; c++) {
        if (c + 1 < NCH) ld(c + 1);
        const float* stg = smem + (c & 1) * STG;
        chunk_mma<2, 2>(stg, stg + TAW, wm, wn, g, t, acc);
        if (c + 1 < NCH) { st(c + 1); __syncthreads(); }
    }

    // B-row sumsq: tasks (r,0),(r,1) sit on adjacent lanes -> pair shuffle
    {
        float sb = sq + __shfl_xor_sync(0xffffffffu, sq, 1);
        if (act && !isA && (lane & 1) == 0) pn2s[(tid - 256) >> 1] = sb;
    }
    __syncthreads();

    if (!isp) {
#pragma unroll
        for (int i = 0; i < 2; i++) {
            int m = m0 + wm + i * 16 + g;
#pragma unroll
            for (int nn = 0; nn < 2; nn++) {
                int n = n0 + wn + nn * 8 + 2 * t;
                float bn0 = bm[n], bn1 = bm[n + 1];
                *(float2*)(out + (size_t)m * P_ + n) =
                    make_float2(acc[i][nn][0] + bn0, acc[i][nn][1] + bn1);
                *(float2*)(out + (size_t)(m + 8) * P_ + n) =
                    make_float2(acc[i][nn][2] + bn0, acc[i][nn][3] + bn1);
            }
        }
        return;
    }

    // proxy: s = 2*dot - fn2 - pn2 in regs -> per-(row, warp) (max, sumexp)
#pragma unroll
    for (int i = 0; i < 2; i++) {
        const int rA = wm + i * 16 + g;
        const int rB = rA + 8;
        const float fa = g_feat_n2[m0 + rA], fb = g_feat_n2[m0 + rB];
        const int ya = y[m0 + rA], yb = y[m0 + rB];
        float sA[4], sB[4];
#pragma unroll
        for (int nn = 0; nn < 2; nn++) {
            int nl = wn + nn * 8 + 2 * t;
            float p0 = pn2s[nl], p1 = pn2s[nl + 1];
            sA[nn * 2 + 0] = 2.f * acc[i][nn][0] - fa - p0;
            sA[nn * 2 + 1] = 2.f * acc[i][nn][1] - fa - p1;
            sB[nn * 2 + 0] = 2.f * acc[i][nn][2] - fb - p0;
            sB[nn * 2 + 1] = 2.f * acc[i][nn][3] - fb - p1;
            int n = n0 + nl;
            if (n     == ya) g_sy[m0 + rA] = sA[nn * 2 + 0];
            if (n + 1 == ya) g_sy[m0 + rA] = sA[nn * 2 + 1];
            if (n     == yb) g_sy[m0 + rB] = sB[nn * 2 + 0];
            if (n + 1 == yb) g_sy[m0 + rB] = sB[nn * 2 + 1];
        }
        float mA = fmaxf(fmaxf(sA[0], sA[1]), fmaxf(sA[2], sA[3]));
        float mB = fmaxf(fmaxf(sB[0], sB[1]), fmaxf(sB[2], sB[3]));
        float eA = expf(sA[0] - mA) + expf(sA[1] - mA)
                 + expf(sA[2] - mA) + expf(sA[3] - mA);
        float eB = expf(sB[0] - mB) + expf(sB[1] - mB)
                 + expf(sB[2] - mB) + expf(sB[3] - mB);
#pragma unroll
        for (int o = 1; o <= 2; o <<= 1) {
            float mA2 = __shfl_xor_sync(0xffffffffu, mA, o);
            float eA2 = __shfl_xor_sync(0xffffffffu, eA, o);
            float mB2 = __shfl_xor_sync(0xffffffffu, mB, o);
            float eB2 = __shfl_xor_sync(0xffffffffu, eB, o);
            float M = fmaxf(mA, mA2);
            eA = eA * expf(mA - M) + eA2 * expf(mA2 - M); mA = M;
            M = fmaxf(mB, mB2);
            eB = eB * expf(mB - M) + eB2 * expf(mB2 - M); mB = M;
        }
        if (t == 0) {
            pmx[rA * 4 + wc] = mA; psm[rA * 4 + wc] = eA;
            pmx[rB * 4 + wc] = mB; psm[rB * 4 + wc] = eB;
        }
    }
    __syncthreads();
    if (tid < 128) {
        float4 m4 = *(const float4*)(pmx + tid * 4);
        float4 s4 = *(const float4*)(psm + tid * 4);
        float M = fmaxf(fmaxf(m4.x, m4.y), fmaxf(m4.z, m4.w));
        float S = s4.x * expf(m4.x - M) + s4.y * expf(m4.y - M)
                + s4.z * expf(m4.z - M) + s4.w * expf(m4.w - M);
        int idx = (m0 + tid) * NT_P + (nt - 32);
        g_pmax[idx] = M;
        g_psum[idx] = S;
    }

    // ---- last-done proxy CTA finalizes loss + reg_e --------------------
    __threadfence();                            // publish partials + g_sy
    __syncthreads();
    if (tid == 0) *flag = (atomicAdd(&g_done, 1) == 63) ? 1 : 0;
    __syncthreads();
    if (*flag == 0) return;
    __threadfence();                            // acquire others' writes

    // 512 threads: 2 per row; q handles 16 n-tiles = 4 float4 of (pmax,psum)
    float* r1 = pmx;                            // reuse smem [256]
    float* r2 = pmx + 256;
    {
        const int b = tid >> 1, q = tid & 1;
        const float4* pm = (const float4*)(g_pmax + b * NT_P + q * 16);
        const float4* ps = (const float4*)(g_psum + b * NT_P + q * 16);
        float4 m0v = pm[0], m1v = pm[1], m2v = pm[2], m3v = pm[3];
        float4 s0v = ps[0], s1v = ps[1], s2v = ps[2], s3v = ps[3];
        float M = fmaxf(fmaxf(fmaxf(m0v.x, m0v.y), fmaxf(m0v.z, m0v.w)),
                        fmaxf(fmaxf(m1v.x, m1v.y), fmaxf(m1v.z, m1v.w)));
        M = fmaxf(M, fmaxf(fmaxf(fmaxf(m2v.x, m2v.y), fmaxf(m2v.z, m2v.w)),
                           fmaxf(fmaxf(m3v.x, m3v.y), fmaxf(m3v.z, m3v.w))));
        float S = s0v.x * expf(m0v.x - M) + s0v.y * expf(m0v.y - M)
                + s0v.z * expf(m0v.z - M) + s0v.w * expf(m0v.w - M)
                + s1v.x * expf(m1v.x - M) + s1v.y * expf(m1v.y - M)
                + s1v.z * expf(m1v.z - M) + s1v.w * expf(m1v.w - M)
                + s2v.x * expf(m2v.x - M) + s2v.y * expf(m2v.y - M)
                + s2v.z * expf(m2v.z - M) + s2v.w * expf(m2v.w - M)
                + s3v.x * expf(m3v.x - M) + s3v.y * expf(m3v.y - M)
                + s3v.z * expf(m3v.z - M) + s3v.w * expf(m3v.w - M);
        float M2 = __shfl_xor_sync(0xffffffffu, M, 1);
        float S2 = __shfl_xor_sync(0xffffffffu, S, 1);
        float Mn = fmaxf(M, M2);
        S = S * expf(M - Mn) + S2 * expf(M2 - Mn);
        if (q == 0) {
            r1[b] = g_sy[b] - Mn - logf(S);     // logp[b, y[b]]
            r2[b] = sqrtf(g_feat_n2[b]);
        }
    }
    __syncthreads();
    for (int stp = 128; stp > 0; stp >>= 1) {
        if (tid < stp) { r1[tid] += r1[tid + stp]; r2[tid] += r2[tid + stp]; }
        __syncthreads();
    }
    if (tid == 0) {
        out[(size_t)B_ * P_]     = -r1[0] / (float)B_;  // loss
        out[(size_t)B_ * P_ + 1] =  r2[0] / (float)B_;  // reg_e
        g_done = 0;                              // reset for graph replay
    }
}

// ---------------- launch ----------------------------------------------------
extern "C" void kernel_launch(void* const* d_in, const int* in_sizes, int n_in,
                              void* d_out, int out_size)
{
    const float* x       = (const float*)d_in[0];
    const int*   y       = (const int*)  d_in[1];
    const float* Wb      = (const float*)d_in[2];
    const float* bb      = (const float*)d_in[3];
    const float* Wm      = (const float*)d_in[4];
    const float* bm      = (const float*)d_in[5];
    const float* proxies = (const float*)d_in[6];
    float* out = (float*)d_out;

    const int SMEM1 = 4 * 64 * RS_W * 4;                             // 45056 B
    const int SMEM2 = (2 * (128 + 64) * RS_W + 64 + 1024 + 4) * 4;   // 71952 B
    cudaFuncSetAttribute(gemm1_mma,  cudaFuncAttributeMaxDynamicSharedMemorySize, SMEM1);
    cudaFuncSetAttribute(gemm23_mma, cudaFuncAttributeMaxDynamicSharedMemorySize, SMEM2);

    // 1) feat partials: (8, 4, 4) = 128 CTAs, 512 thr
    gemm1_mma<<<dim3(D_ / 64, B_ / 64, SPLITK), 512, SMEM1>>>(x, Wb);
    // 2) combine + bias + round + row norms
    combine_feat_kernel<<<B_ / 8, 256>>>(bb);
    // 3) fused out-head + proxy softmax partials + last-CTA finalize
    gemm23_mma<<<dim3(64, B_ / 128), 512, SMEM2>>>(Wm, bm, proxies, y, out);
}